// round 3
// baseline (speedup 1.0000x reference)
#include <cuda_runtime.h>

#define NSEG 256
#define D 128
#define OUT_ELEMS (NSEG * D)

// Scratch for per-segment element counts (alloc-free rule: __device__ global).
__device__ int g_counts[NSEG];

// ---------------------------------------------------------------------------
// Pass 0: zero output sums and counts (d_out is poisoned by the harness).
// ---------------------------------------------------------------------------
__global__ void zero_kernel(float* __restrict__ out) {
    int i = blockIdx.x * blockDim.x + threadIdx.x;
    if (i < OUT_ELEMS) out[i] = 0.0f;
    if (i < NSEG) g_counts[i] = 0;
}

// ---------------------------------------------------------------------------
// Pass 1: segmented sum. One warp owns a contiguous row chunk; lane l holds
// float4 column-slice [4l, 4l+4). Register accumulation; atomics only at
// segment boundaries / chunk end (sorted ids make these rare).
// ---------------------------------------------------------------------------
__device__ __forceinline__ void flush_acc(float* __restrict__ out, int seg_id,
                                          int lane, const float4& acc, int cnt) {
    float* p = out + seg_id * D + lane * 4;
    atomicAdd(p + 0, acc.x);
    atomicAdd(p + 1, acc.y);
    atomicAdd(p + 2, acc.z);
    atomicAdd(p + 3, acc.w);
    if (lane == 0) atomicAdd(&g_counts[seg_id], cnt);
}

__global__ __launch_bounds__(256, 8) void segsum_kernel(
    const float4* __restrict__ inp,   // (n, 32) float4 view of (n, 128) float
    const int* __restrict__ seg,      // (n,) sorted segment ids
    float* __restrict__ out,          // (256, 128) sums
    int n)
{
    const int lane = threadIdx.x & 31;
    const int warp_global = (blockIdx.x * blockDim.x + threadIdx.x) >> 5;
    const int num_warps = (gridDim.x * blockDim.x) >> 5;

    const int rows_per_warp = (n + num_warps - 1) / num_warps;
    int r = warp_global * rows_per_warp;
    const int r1 = min(n, r + rows_per_warp);
    if (r >= r1) return;

    float4 acc = make_float4(0.0f, 0.0f, 0.0f, 0.0f);
    int cnt = 0;
    int cur = seg[r];

    // Fast path: 4 rows per iteration. Issue all loads first (MLP), then
    // accumulate. Sorted ids => s0==cur && s3==cur implies s1,s2==cur.
    while (r + 4 <= r1) {
        int s0 = seg[r];
        int s3 = seg[r + 3];
        float4 v0 = inp[(size_t)(r + 0) * 32 + lane];
        float4 v1 = inp[(size_t)(r + 1) * 32 + lane];
        float4 v2 = inp[(size_t)(r + 2) * 32 + lane];
        float4 v3 = inp[(size_t)(r + 3) * 32 + lane];
        if (s0 == cur && s3 == cur) {
            acc.x += (v0.x + v1.x) + (v2.x + v3.x);
            acc.y += (v0.y + v1.y) + (v2.y + v3.y);
            acc.z += (v0.z + v1.z) + (v2.z + v3.z);
            acc.w += (v0.w + v1.w) + (v2.w + v3.w);
            cnt += 4;
        } else {
            // Boundary inside this quad: process row-by-row.
            int s1 = seg[r + 1];
            int s2 = seg[r + 2];
            int   ss[4] = {s0, s1, s2, s3};
            float4 vv[4] = {v0, v1, v2, v3};
            #pragma unroll
            for (int i = 0; i < 4; ++i) {
                if (ss[i] != cur) {
                    flush_acc(out, cur, lane, acc, cnt);
                    acc = make_float4(0.0f, 0.0f, 0.0f, 0.0f);
                    cnt = 0;
                    cur = ss[i];
                }
                acc.x += vv[i].x; acc.y += vv[i].y;
                acc.z += vv[i].z; acc.w += vv[i].w;
                cnt++;
            }
        }
        r += 4;
    }

    // Tail rows.
    for (; r < r1; ++r) {
        int s = seg[r];
        float4 v = inp[(size_t)r * 32 + lane];
        if (s != cur) {
            flush_acc(out, cur, lane, acc, cnt);
            acc = make_float4(0.0f, 0.0f, 0.0f, 0.0f);
            cnt = 0;
            cur = s;
        }
        acc.x += v.x; acc.y += v.y; acc.z += v.z; acc.w += v.w;
        cnt++;
    }

    flush_acc(out, cur, lane, acc, cnt);
}

// ---------------------------------------------------------------------------
// Pass 2: divide sums by counts (mean).
// ---------------------------------------------------------------------------
__global__ void finalize_kernel(float* __restrict__ out) {
    int i = blockIdx.x * blockDim.x + threadIdx.x;
    if (i >= OUT_ELEMS) return;
    int s = i >> 7;  // / D
    int c = g_counts[s];
    if (c < 1) c = 1;
    out[i] = out[i] / (float)c;
}

// ---------------------------------------------------------------------------
// Launch. Inputs per metadata order: d_in[0] = inp (float32, n*128),
// d_in[1] = batch_seg (int32, n). Output: (256, 128) float32.
// ---------------------------------------------------------------------------
extern "C" void kernel_launch(void* const* d_in, const int* in_sizes, int n_in,
                              void* d_out, int out_size) {
    const float* inp = (const float*)d_in[0];
    const int* seg = (const int*)d_in[1];
    float* out = (float*)d_out;
    const int n = in_sizes[1];  // number of rows

    // Pass 0: zero sums + counts.
    zero_kernel<<<(OUT_ELEMS + 255) / 256, 256>>>(out);

    // Pass 1: segmented sum. 148 SMs x 8 CTAs of 256 threads.
    const int blocks = 148 * 8;
    segsum_kernel<<<blocks, 256>>>((const float4*)inp, seg, out, n);

    // Pass 2: mean.
    finalize_kernel<<<(OUT_ELEMS + 255) / 256, 256>>>(out);
}